// round 5
// baseline (speedup 1.0000x reference)
#include <cuda_runtime.h>
#include <math.h>
#include <stdint.h>

// Problem constants
#define BHALF 8192            // B
#define N     16384           // 2B
#define TILE  128
#define NT    (N / TILE)      // 128 tiles
#define NTRI  (NT * (NT + 1) / 2)        // 8256 triangular blocks
#define EXPDIAG 7.389056098930650f       // exp(2) = exp(sim_ii / T)
#define NEG_INV_C (-0.34657359027997264f) // -1/(2*log2(e)) = -ln2/2
#define TEMP_EPS 0.01f

// Scratch (deterministic: every slot has exactly one writer)
__device__ float g_part[NT * N];          // 8 MB partial row sums (L2-resident)
__device__ float g_blocksum[64];
__device__ float g_tail;
__device__ int   g_done = 0;

// ---------------- packed f32x2 helpers (sm_100 family) ----------------
__device__ __forceinline__ unsigned long long pk2(float lo, float hi) {
    unsigned long long r;
    asm("mov.b64 %0, {%1, %2};" : "=l"(r) : "f"(lo), "f"(hi));
    return r;
}
__device__ __forceinline__ float lo2(unsigned long long v) {
    float f; asm("{ .reg .f32 t; mov.b64 {%0, t}, %1; }" : "=f"(f) : "l"(v)); return f;
}
__device__ __forceinline__ float hi2(unsigned long long v) {
    float f; asm("{ .reg .f32 t; mov.b64 {t, %0}, %1; }" : "=f"(f) : "l"(v)); return f;
}
__device__ __forceinline__ unsigned long long add2(unsigned long long a, unsigned long long b) {
    unsigned long long r;
    asm("add.rn.f32x2 %0, %1, %2;" : "=l"(r) : "l"(a), "l"(b));
    return r;
}
__device__ __forceinline__ unsigned long long mul2(unsigned long long a, unsigned long long b) {
    unsigned long long r;
    asm("mul.rn.f32x2 %0, %1, %2;" : "=l"(r) : "l"(a), "l"(b));
    return r;
}
__device__ __forceinline__ unsigned long long fma2(unsigned long long a, unsigned long long b,
                                                   unsigned long long c) {
    unsigned long long r;
    asm("fma.rn.f32x2 %0, %1, %2, %3;" : "=l"(r) : "l"(a), "l"(b), "l"(c));
    return r;
}
__device__ __forceinline__ float ex2a(float x) {
    float r;
    asm("ex2.approx.ftz.f32 %0, %1;" : "=f"(r) : "f"(x));
    return r;
}

// ---------------------------------------------------------------------------
// Kernel A: symmetric 128x128 tile kernel, 512 threads, 4 rows x 8 cols per
// thread (half the register state of the 256-thread version -> 2 blocks/SM
// = 32 warps/SM = 8 warps/SMSP for latency cover).
// Per 2 pairs: 8 fma-pipe ops + 4 alu + 2 MUFU.EX2.
// ---------------------------------------------------------------------------
__global__ __launch_bounds__(512, 2) void tile_kernel(
    const float* __restrict__ emb_i, const float* __restrict__ emb_j)
{
    // decode triangular (a, b) from linear block id
    const int k = blockIdx.x;
    float disc = (float)((2 * NT + 1) * (2 * NT + 1) - 8 * k);
    int a = (int)(((float)(2 * NT + 1) - sqrtf(disc)) * 0.5f);
    a = max(0, min(a, NT - 1));
    while (a > 0 && k < a * NT - (a * (a - 1)) / 2) a--;
    while (k >= (a + 1) * NT - ((a + 1) * a) / 2) a++;
    const int b = a + (k - (a * NT - (a * (a - 1)) / 2));

    __shared__ float ra[TILE];
    __shared__ float rbn[TILE];           // NEGATED b-tile values
    __shared__ float red[32][TILE + 1];   // reduction scratch (rows use 16)

    const int t = threadIdx.x;

    if (t < TILE) {
        int g = a * TILE + t;
        ra[t] = (g < BHALF) ? emb_i[g] : emb_j[g - BHALF];
    } else if (t < 2 * TILE) {
        int t2 = t - TILE;
        int g = b * TILE + t2;
        float v = (g < BHALF) ? emb_i[g] : emb_j[g - BHALF];
        rbn[t2] = -v;
    }
    __syncthreads();

    const int tx = t & 15;      // 16 thread-cols  (8 cols each)
    const int ty = t >> 4;      // 32 thread-rows  (4 rows each)

    unsigned long long riP[4], rjn[4];
#pragma unroll
    for (int y = 0; y < 4; y++) { float v = ra[ty * 4 + y]; riP[y] = pk2(v, v); }
#pragma unroll
    for (int x2 = 0; x2 < 4; x2++)
        rjn[x2] = pk2(rbn[tx * 8 + 2 * x2], rbn[tx * 8 + 2 * x2 + 1]);

    const unsigned long long cN   = pk2(NEG_INV_C, NEG_INV_C);
    const unsigned long long two2 = pk2(2.0f, 2.0f);

    unsigned long long rowP[4], colP[4];
#pragma unroll
    for (int y = 0; y < 4; y++) { rowP[y] = 0ULL; colP[y] = 0ULL; }

#pragma unroll
    for (int y = 0; y < 4; y++) {
        const unsigned long long rip = riP[y];
#pragma unroll
        for (int x2 = 0; x2 < 4; x2++) {
            unsigned long long df = add2(rip, rjn[x2]);              // ri - rj
            df &= 0x7FFFFFFF7FFFFFFFULL;                              // |.| per half
            unsigned long long sn = fma2(df, cN, cN);                 // -(1+d)/C
            uint32_t bl = (uint32_t)sn;
            uint32_t bh = (uint32_t)(sn >> 32);
            unsigned long long r = pk2(__uint_as_float(0xFEF311C3u - bl),
                                       __uint_as_float(0xFEF311C3u - bh));
            unsigned long long tt = fma2(sn, r, two2);                // 2 - |s|r
            r = mul2(r, tt);
            tt = fma2(sn, r, two2);
            r = mul2(r, tt);                                          // ~ C/(1+d)
            unsigned long long e2 = pk2(ex2a(lo2(r)), ex2a(hi2(r)));
            rowP[y]  = add2(rowP[y],  e2);
            colP[x2] = add2(colP[x2], e2);
        }
    }

    // --- deterministic row-partial reduction (across the 16 thread-cols) ---
#pragma unroll
    for (int y = 0; y < 4; y++)
        red[tx][ty * 4 + y] = lo2(rowP[y]) + hi2(rowP[y]);
    __syncthreads();
    if (t < TILE) {
        float s = 0.0f;
#pragma unroll
        for (int kk = 0; kk < 16; kk++) s += red[kk][t];
        g_part[b * N + a * TILE + t] = s;
    }
    __syncthreads();

    // --- deterministic col-partial reduction (across the 32 thread-rows) ---
#pragma unroll
    for (int x2 = 0; x2 < 4; x2++) {
        red[ty][tx * 8 + 2 * x2]     = lo2(colP[x2]);
        red[ty][tx * 8 + 2 * x2 + 1] = hi2(colP[x2]);
    }
    __syncthreads();
    if (a != b && t < TILE) {
        float s = 0.0f;
#pragma unroll
        for (int kk = 0; kk < 32; kk++) s += red[kk][t];
        g_part[a * N + b * TILE + t] = s;
    }
}

// ---------------------------------------------------------------------------
// Kernel B: 65 blocks x 256 threads.
//   blocks 0..63 : per-row denominator -> __logf -> block sum  (256 rows each)
//   block 64     : prosody softmax + positives tail (fast intrinsics)
// Last-finishing block combines everything and writes out (fixed-order sum
// -> deterministic regardless of which block combines).
// ---------------------------------------------------------------------------
__global__ __launch_bounds__(256) void reduce_kernel(
    const float* __restrict__ emb_i, const float* __restrict__ emb_j,
    const float* __restrict__ pro_i, const float* __restrict__ pro_j,
    float* __restrict__ out)
{
    __shared__ float sred[256];
    const int t = threadIdx.x;
    const int role = blockIdx.x;

    if (role < 64) {
        // ---- row-log reduction: rows [role*256, role*256+256) ----
        const int i = role * 256 + t;
        float s = 0.0f;
#pragma unroll 16
        for (int kk = 0; kk < NT; kk++) s += g_part[kk * N + i];
        sred[t] = __logf(s - EXPDIAG);        // remove diagonal term exp(2)
        __syncthreads();
        for (int off = 128; off > 0; off >>= 1) {
            if (t < off) sred[t] += sred[t + off];
            __syncthreads();
        }
        if (t == 0) g_blocksum[role] = sred[0];
    } else {
        // ---- prosody softmax + positives tail (block 64) ----
        float mx = -1.0f;
        for (int bb = t; bb < BHALF; bb += 256)
            mx = fmaxf(mx, fabsf(pro_i[bb] - pro_j[bb]));
        sred[t] = mx;
        __syncthreads();
        for (int off = 128; off > 0; off >>= 1) {
            if (t < off) sred[t] = fmaxf(sred[t], sred[t + off]);
            __syncthreads();
        }
        mx = sred[0];
        __syncthreads();

        float se = 0.0f;
        for (int bb = t; bb < BHALF; bb += 256)
            se += __expf(fabsf(pro_i[bb] - pro_j[bb]) - mx);
        sred[t] = se;
        __syncthreads();
        for (int off = 128; off > 0; off >>= 1) {
            if (t < off) sred[t] += sred[t + off];
            __syncthreads();
        }
        const float invZ = 1.0f / sred[0];
        __syncthreads();

        float lp = 0.0f;
        for (int bb = t; bb < BHALF; bb += 256) {
            float pdv = fabsf(pro_i[bb] - pro_j[bb]);
            lp += __logf(__expf(pdv - mx) * invZ + TEMP_EPS);
            lp += __logf(1.0f + fabsf(emb_i[bb] - emb_j[bb]));
        }
        sred[t] = lp;
        __syncthreads();
        for (int off = 128; off > 0; off >>= 1) {
            if (t < off) sred[t] += sred[t + off];
            __syncthreads();
        }
        if (t == 0) g_tail = sred[0];
    }

    // ---- last block combines (fixed-order read -> deterministic) ----
    __threadfence();
    __syncthreads();
    if (t == 0) {
        int old = atomicAdd(&g_done, 1);
        if (old == 64) {                       // all 65 blocks finished
            __threadfence();
            float L1 = 0.0f;
            volatile float* bs = g_blocksum;
#pragma unroll
            for (int kk = 0; kk < 64; kk++) L1 += bs[kk];
            out[0] = (L1 + 2.0f * (*(volatile float*)&g_tail)) / (float)N;
            g_done = 0;                        // reset for next graph replay
        }
    }
}

// ---------------------------------------------------------------------------
extern "C" void kernel_launch(void* const* d_in, const int* in_sizes, int n_in,
                              void* d_out, int out_size)
{
    const float* emb_i = (const float*)d_in[0];
    const float* emb_j = (const float*)d_in[1];
    const float* pro_i = (const float*)d_in[2];
    const float* pro_j = (const float*)d_in[3];
    float* out = (float*)d_out;

    tile_kernel<<<NTRI, 512>>>(emb_i, emb_j);
    reduce_kernel<<<65, 256>>>(emb_i, emb_j, pro_i, pro_j, out);
}

// round 6
// speedup vs baseline: 1.3952x; 1.3952x over previous
#include <cuda_runtime.h>
#include <math.h>
#include <stdint.h>

// Problem constants
#define BHALF 8192            // B
#define N     16384           // 2B
#define TILE  128
#define NT    (N / TILE)      // 128 tiles
#define NTRI  (NT * (NT + 1) / 2)        // 8256 triangular blocks
#define NRED  129                         // 128 rowlog blocks + 1 prosody
#define EXPDIAG 7.389056098930650f       // exp(2) = exp(sim_ii / T)
#define NEG_INV_C (-0.34657359027997264f) // -1/(2*log2(e)) = -ln2/2
#define TEMP_EPS 0.01f

// Scratch (deterministic: every slot has exactly one writer)
__device__ float g_part[NT * N];          // 8 MB partial row sums (L2-resident)
__device__ float g_blocksum[128];
__device__ float g_tail;
__device__ int   g_done = 0;

// ---------------- packed f32x2 helpers (sm_100 family) ----------------
__device__ __forceinline__ unsigned long long pk2(float lo, float hi) {
    unsigned long long r;
    asm("mov.b64 %0, {%1, %2};" : "=l"(r) : "f"(lo), "f"(hi));
    return r;
}
__device__ __forceinline__ float lo2(unsigned long long v) {
    float f; asm("{ .reg .f32 t; mov.b64 {%0, t}, %1; }" : "=f"(f) : "l"(v)); return f;
}
__device__ __forceinline__ float hi2(unsigned long long v) {
    float f; asm("{ .reg .f32 t; mov.b64 {t, %0}, %1; }" : "=f"(f) : "l"(v)); return f;
}
__device__ __forceinline__ unsigned long long add2(unsigned long long a, unsigned long long b) {
    unsigned long long r;
    asm("add.rn.f32x2 %0, %1, %2;" : "=l"(r) : "l"(a), "l"(b));
    return r;
}
__device__ __forceinline__ unsigned long long mul2(unsigned long long a, unsigned long long b) {
    unsigned long long r;
    asm("mul.rn.f32x2 %0, %1, %2;" : "=l"(r) : "l"(a), "l"(b));
    return r;
}
__device__ __forceinline__ unsigned long long fma2(unsigned long long a, unsigned long long b,
                                                   unsigned long long c) {
    unsigned long long r;
    asm("fma.rn.f32x2 %0, %1, %2, %3;" : "=l"(r) : "l"(a), "l"(b), "l"(c));
    return r;
}
__device__ __forceinline__ float ex2a(float x) {
    float r;
    asm("ex2.approx.ftz.f32 %0, %1;" : "=f"(r) : "f"(x));
    return r;
}

// ---------------------------------------------------------------------------
// Kernel A: symmetric tile kernel — EXACT copy of the proven 57.3us version.
// 256 threads, 8 rows x 8 cols per thread, natural 80 regs -> 3 blocks/SM.
// Per 2 pairs: 8 fma-pipe ops + 4 alu + 2 MUFU.EX2 — fma & MUFU co-bound.
// ---------------------------------------------------------------------------
__global__ __launch_bounds__(256, 2) void tile_kernel(
    const float* __restrict__ emb_i, const float* __restrict__ emb_j)
{
    // decode triangular (a, b) from linear block id
    const int k = blockIdx.x;
    float disc = (float)((2 * NT + 1) * (2 * NT + 1) - 8 * k);
    int a = (int)(((float)(2 * NT + 1) - sqrtf(disc)) * 0.5f);
    a = max(0, min(a, NT - 1));
    while (a > 0 && k < a * NT - (a * (a - 1)) / 2) a--;
    while (k >= (a + 1) * NT - ((a + 1) * a) / 2) a++;
    const int b = a + (k - (a * NT - (a * (a - 1)) / 2));

    __shared__ float ra[TILE];
    __shared__ float rbn[TILE];           // NEGATED b-tile values
    __shared__ float red[16][TILE + 1];

    const int t = threadIdx.x;

    if (t < TILE) {
        int g = a * TILE + t;
        ra[t] = (g < BHALF) ? emb_i[g] : emb_j[g - BHALF];
    } else {
        int t2 = t - TILE;
        int g = b * TILE + t2;
        float v = (g < BHALF) ? emb_i[g] : emb_j[g - BHALF];
        rbn[t2] = -v;
    }
    __syncthreads();

    const int tx = t & 15;
    const int ty = t >> 4;

    unsigned long long riP[8], rjn[4];
#pragma unroll
    for (int y = 0; y < 8; y++) { float v = ra[ty * 8 + y]; riP[y] = pk2(v, v); }
#pragma unroll
    for (int x2 = 0; x2 < 4; x2++)
        rjn[x2] = pk2(rbn[tx * 8 + 2 * x2], rbn[tx * 8 + 2 * x2 + 1]);

    const unsigned long long cN   = pk2(NEG_INV_C, NEG_INV_C);
    const unsigned long long two2 = pk2(2.0f, 2.0f);

    unsigned long long rowP[8], colP[4];
#pragma unroll
    for (int y = 0; y < 8; y++) rowP[y] = 0ULL;
#pragma unroll
    for (int x2 = 0; x2 < 4; x2++) colP[x2] = 0ULL;

#pragma unroll
    for (int y = 0; y < 8; y++) {
        const unsigned long long rip = riP[y];
#pragma unroll
        for (int x2 = 0; x2 < 4; x2++) {
            unsigned long long df = add2(rip, rjn[x2]);              // ri - rj
            df &= 0x7FFFFFFF7FFFFFFFULL;                              // |.| per half
            unsigned long long sn = fma2(df, cN, cN);                 // -(1+d)/C
            uint32_t bl = (uint32_t)sn;
            uint32_t bh = (uint32_t)(sn >> 32);
            unsigned long long r = pk2(__uint_as_float(0xFEF311C3u - bl),
                                       __uint_as_float(0xFEF311C3u - bh));
            unsigned long long tt = fma2(sn, r, two2);                // 2 - |s|r
            r = mul2(r, tt);
            tt = fma2(sn, r, two2);
            r = mul2(r, tt);                                          // ~ C/(1+d)
            unsigned long long e2 = pk2(ex2a(lo2(r)), ex2a(hi2(r)));
            rowP[y]  = add2(rowP[y],  e2);
            colP[x2] = add2(colP[x2], e2);
        }
    }

    // --- deterministic row-partial reduction (across the 16 thread-cols) ---
#pragma unroll
    for (int y = 0; y < 8; y++)
        red[tx][ty * 8 + y] = lo2(rowP[y]) + hi2(rowP[y]);
    __syncthreads();
    if (t < TILE) {
        float s = 0.0f;
#pragma unroll
        for (int kk = 0; kk < 16; kk++) s += red[kk][t];
        g_part[b * N + a * TILE + t] = s;
    }
    __syncthreads();

    // --- deterministic col-partial reduction (across the 16 thread-rows) ---
#pragma unroll
    for (int x2 = 0; x2 < 4; x2++) {
        red[ty][tx * 8 + 2 * x2]     = lo2(colP[x2]);
        red[ty][tx * 8 + 2 * x2 + 1] = hi2(colP[x2]);
    }
    __syncthreads();
    if (a != b && t < TILE) {
        float s = 0.0f;
#pragma unroll
        for (int kk = 0; kk < 16; kk++) s += red[kk][t];
        g_part[a * N + b * TILE + t] = s;
    }
}

// ---------------------------------------------------------------------------
// Kernel B: 129 blocks x 256 threads.
//   blocks 0..127 : 128 rows each, 2 threads/row (fixed halves of the
//                   128-partial sum -> deterministic) -> __logf -> block sum
//   block 128     : prosody softmax + positives tail (fast intrinsics)
// Last-finishing block combines everything (fixed-order read) -> out.
// ---------------------------------------------------------------------------
__global__ __launch_bounds__(256) void reduce_kernel(
    const float* __restrict__ emb_i, const float* __restrict__ emb_j,
    const float* __restrict__ pro_i, const float* __restrict__ pro_j,
    float* __restrict__ out)
{
    __shared__ float sred[256];
    __shared__ float shalf[256];
    const int t = threadIdx.x;
    const int role = blockIdx.x;

    if (role < 128) {
        // ---- row-log reduction: rows [role*128, role*128+128) ----
        const int row  = role * 128 + (t & 127);
        const int half = t >> 7;               // 0: kk 0..63, 1: kk 64..127
        float s = 0.0f;
#pragma unroll 16
        for (int kk = half * 64; kk < half * 64 + 64; kk++)
            s += g_part[kk * N + row];
        shalf[t] = s;
        __syncthreads();
        float l = 0.0f;
        if (t < 128) {
            float full = shalf[t] + shalf[t + 128];   // fixed order: deterministic
            l = __logf(full - EXPDIAG);               // remove diagonal exp(2)
        }
        sred[t] = l;                                   // t>=128 contribute 0
        __syncthreads();
        for (int off = 128; off > 0; off >>= 1) {
            if (t < off) sred[t] += sred[t + off];
            __syncthreads();
        }
        if (t == 0) g_blocksum[role] = sred[0];
    } else {
        // ---- prosody softmax + positives tail (block 128) ----
        float mx = -1.0f;
        for (int bb = t; bb < BHALF; bb += 256)
            mx = fmaxf(mx, fabsf(pro_i[bb] - pro_j[bb]));
        sred[t] = mx;
        __syncthreads();
        for (int off = 128; off > 0; off >>= 1) {
            if (t < off) sred[t] = fmaxf(sred[t], sred[t + off]);
            __syncthreads();
        }
        mx = sred[0];
        __syncthreads();

        float se = 0.0f;
        for (int bb = t; bb < BHALF; bb += 256)
            se += __expf(fabsf(pro_i[bb] - pro_j[bb]) - mx);
        sred[t] = se;
        __syncthreads();
        for (int off = 128; off > 0; off >>= 1) {
            if (t < off) sred[t] += sred[t + off];
            __syncthreads();
        }
        const float invZ = 1.0f / sred[0];
        __syncthreads();

        float lp = 0.0f;
        for (int bb = t; bb < BHALF; bb += 256) {
            float pdv = fabsf(pro_i[bb] - pro_j[bb]);
            lp += __logf(__expf(pdv - mx) * invZ + TEMP_EPS);
            lp += __logf(1.0f + fabsf(emb_i[bb] - emb_j[bb]));
        }
        sred[t] = lp;
        __syncthreads();
        for (int off = 128; off > 0; off >>= 1) {
            if (t < off) sred[t] += sred[t + off];
            __syncthreads();
        }
        if (t == 0) g_tail = sred[0];
    }

    // ---- last block combines (fixed-order read -> deterministic) ----
    __threadfence();
    __syncthreads();
    if (t == 0) {
        int old = atomicAdd(&g_done, 1);
        if (old == NRED - 1) {                 // all 129 blocks finished
            __threadfence();
            float L1 = 0.0f;
            volatile float* bs = g_blocksum;
#pragma unroll
            for (int kk = 0; kk < 128; kk++) L1 += bs[kk];
            out[0] = (L1 + 2.0f * (*(volatile float*)&g_tail)) / (float)N;
            g_done = 0;                        // reset for next graph replay
        }
    }
}

// ---------------------------------------------------------------------------
extern "C" void kernel_launch(void* const* d_in, const int* in_sizes, int n_in,
                              void* d_out, int out_size)
{
    const float* emb_i = (const float*)d_in[0];
    const float* emb_j = (const float*)d_in[1];
    const float* pro_i = (const float*)d_in[2];
    const float* pro_j = (const float*)d_in[3];
    float* out = (float*)d_out;

    tile_kernel<<<NTRI, 256>>>(emb_i, emb_j);
    reduce_kernel<<<NRED, 256>>>(emb_i, emb_j, pro_i, pro_j, out);
}

// round 7
// speedup vs baseline: 1.4534x; 1.0418x over previous
#include <cuda_runtime.h>
#include <math.h>
#include <stdint.h>

// Problem constants
#define BHALF 8192            // B
#define N     16384           // 2B
#define TILE  128
#define NT    (N / TILE)      // 128 tiles
#define NTRI  (NT * (NT + 1) / 2)        // 8256 triangular blocks
#define EXPDIAG 7.389056098930650f       // exp(2) = exp(sim_ii / T)
#define NEG_INV_C (-0.34657359027997264f) // -1/(2*log2(e)) = -ln2/2
#define TEMP_EPS 0.01f

// Scratch (deterministic: every slot has exactly one writer)
__device__ float g_part[NT * N];          // 8 MB partial row sums (L2-resident)
__device__ float g_blocksum[64];
__device__ float g_tail;

// ---------------- packed f32x2 helpers (sm_100 family) ----------------
__device__ __forceinline__ unsigned long long pk2(float lo, float hi) {
    unsigned long long r;
    asm("mov.b64 %0, {%1, %2};" : "=l"(r) : "f"(lo), "f"(hi));
    return r;
}
__device__ __forceinline__ float lo2(unsigned long long v) {
    float f; asm("{ .reg .f32 t; mov.b64 {%0, t}, %1; }" : "=f"(f) : "l"(v)); return f;
}
__device__ __forceinline__ float hi2(unsigned long long v) {
    float f; asm("{ .reg .f32 t; mov.b64 {t, %0}, %1; }" : "=f"(f) : "l"(v)); return f;
}
__device__ __forceinline__ unsigned long long add2(unsigned long long a, unsigned long long b) {
    unsigned long long r;
    asm("add.rn.f32x2 %0, %1, %2;" : "=l"(r) : "l"(a), "l"(b));
    return r;
}
__device__ __forceinline__ unsigned long long mul2(unsigned long long a, unsigned long long b) {
    unsigned long long r;
    asm("mul.rn.f32x2 %0, %1, %2;" : "=l"(r) : "l"(a), "l"(b));
    return r;
}
__device__ __forceinline__ unsigned long long fma2(unsigned long long a, unsigned long long b,
                                                   unsigned long long c) {
    unsigned long long r;
    asm("fma.rn.f32x2 %0, %1, %2, %3;" : "=l"(r) : "l"(a), "l"(b), "l"(c));
    return r;
}
__device__ __forceinline__ float ex2a(float x) {
    float r;
    asm("ex2.approx.ftz.f32 %0, %1;" : "=f"(r) : "f"(x));
    return r;
}

// ---------------------------------------------------------------------------
// Kernel A: symmetric tile kernel. Identical body to the proven 57.3us
// version; ONLY change is __launch_bounds__(256, 3): reg cap 85 >= natural 80
// (no spill) while guaranteeing 3 resident blocks -> 6 warps/SMSP for
// latency cover (was ~4).
// Per 2 pairs: 8 fma-pipe ops + 4 alu + 2 MUFU.EX2 — fma & MUFU co-bound.
// ---------------------------------------------------------------------------
__global__ __launch_bounds__(256, 3) void tile_kernel(
    const float* __restrict__ emb_i, const float* __restrict__ emb_j)
{
    // decode triangular (a, b) from linear block id
    const int k = blockIdx.x;
    float disc = (float)((2 * NT + 1) * (2 * NT + 1) - 8 * k);
    int a = (int)(((float)(2 * NT + 1) - sqrtf(disc)) * 0.5f);
    a = max(0, min(a, NT - 1));
    while (a > 0 && k < a * NT - (a * (a - 1)) / 2) a--;
    while (k >= (a + 1) * NT - ((a + 1) * a) / 2) a++;
    const int b = a + (k - (a * NT - (a * (a - 1)) / 2));

    __shared__ float ra[TILE];
    __shared__ float rbn[TILE];           // NEGATED b-tile values
    __shared__ float red[16][TILE + 1];

    const int t = threadIdx.x;

    if (t < TILE) {
        int g = a * TILE + t;
        ra[t] = (g < BHALF) ? emb_i[g] : emb_j[g - BHALF];
    } else {
        int t2 = t - TILE;
        int g = b * TILE + t2;
        float v = (g < BHALF) ? emb_i[g] : emb_j[g - BHALF];
        rbn[t2] = -v;
    }
    __syncthreads();

    const int tx = t & 15;
    const int ty = t >> 4;

    unsigned long long riP[8], rjn[4];
#pragma unroll
    for (int y = 0; y < 8; y++) { float v = ra[ty * 8 + y]; riP[y] = pk2(v, v); }
#pragma unroll
    for (int x2 = 0; x2 < 4; x2++)
        rjn[x2] = pk2(rbn[tx * 8 + 2 * x2], rbn[tx * 8 + 2 * x2 + 1]);

    const unsigned long long cN   = pk2(NEG_INV_C, NEG_INV_C);
    const unsigned long long two2 = pk2(2.0f, 2.0f);

    unsigned long long rowP[8], colP[4];
#pragma unroll
    for (int y = 0; y < 8; y++) rowP[y] = 0ULL;
#pragma unroll
    for (int x2 = 0; x2 < 4; x2++) colP[x2] = 0ULL;

#pragma unroll
    for (int y = 0; y < 8; y++) {
        const unsigned long long rip = riP[y];
#pragma unroll
        for (int x2 = 0; x2 < 4; x2++) {
            unsigned long long df = add2(rip, rjn[x2]);              // ri - rj
            df &= 0x7FFFFFFF7FFFFFFFULL;                              // |.| per half
            unsigned long long sn = fma2(df, cN, cN);                 // -(1+d)/C
            uint32_t bl = (uint32_t)sn;
            uint32_t bh = (uint32_t)(sn >> 32);
            unsigned long long r = pk2(__uint_as_float(0xFEF311C3u - bl),
                                       __uint_as_float(0xFEF311C3u - bh));
            unsigned long long tt = fma2(sn, r, two2);                // 2 - |s|r
            r = mul2(r, tt);
            tt = fma2(sn, r, two2);
            r = mul2(r, tt);                                          // ~ C/(1+d)
            unsigned long long e2 = pk2(ex2a(lo2(r)), ex2a(hi2(r)));
            rowP[y]  = add2(rowP[y],  e2);
            colP[x2] = add2(colP[x2], e2);
        }
    }

    // --- deterministic row-partial reduction (across the 16 thread-cols) ---
#pragma unroll
    for (int y = 0; y < 8; y++)
        red[tx][ty * 8 + y] = lo2(rowP[y]) + hi2(rowP[y]);
    __syncthreads();
    if (t < TILE) {
        float s = 0.0f;
#pragma unroll
        for (int kk = 0; kk < 16; kk++) s += red[kk][t];
        g_part[b * N + a * TILE + t] = s;
    }
    __syncthreads();

    // --- deterministic col-partial reduction (across the 16 thread-rows) ---
#pragma unroll
    for (int x2 = 0; x2 < 4; x2++) {
        red[ty][tx * 8 + 2 * x2]     = lo2(colP[x2]);
        red[ty][tx * 8 + 2 * x2 + 1] = hi2(colP[x2]);
    }
    __syncthreads();
    if (a != b && t < TILE) {
        float s = 0.0f;
#pragma unroll
        for (int kk = 0; kk < 16; kk++) s += red[kk][t];
        g_part[a * N + b * TILE + t] = s;
    }
}

// ---------------------------------------------------------------------------
// Kernel B: 65 blocks x 256 threads (R4-proven tail).
//   blocks 0..63 : per-row denominator -> __logf -> block sum  (256 rows each)
//   block 64     : prosody softmax + positives tail (fast intrinsics)
// ---------------------------------------------------------------------------
__global__ __launch_bounds__(256) void reduce_kernel(
    const float* __restrict__ emb_i, const float* __restrict__ emb_j,
    const float* __restrict__ pro_i, const float* __restrict__ pro_j)
{
    __shared__ float sred[256];
    const int t = threadIdx.x;
    const int role = blockIdx.x;

    if (role < 64) {
        // ---- row-log reduction: rows [role*256, role*256+256) ----
        const int i = role * 256 + t;
        float s = 0.0f;
#pragma unroll 16
        for (int kk = 0; kk < NT; kk++) s += g_part[kk * N + i];
        sred[t] = __logf(s - EXPDIAG);        // remove diagonal term exp(2)
        __syncthreads();
        for (int off = 128; off > 0; off >>= 1) {
            if (t < off) sred[t] += sred[t + off];
            __syncthreads();
        }
        if (t == 0) g_blocksum[role] = sred[0];
        return;
    }

    // ---- prosody softmax + positives tail (block 64) ----
    float mx = -1.0f;
    for (int bb = t; bb < BHALF; bb += 256)
        mx = fmaxf(mx, fabsf(pro_i[bb] - pro_j[bb]));
    sred[t] = mx;
    __syncthreads();
    for (int off = 128; off > 0; off >>= 1) {
        if (t < off) sred[t] = fmaxf(sred[t], sred[t + off]);
        __syncthreads();
    }
    mx = sred[0];
    __syncthreads();

    float se = 0.0f;
    for (int bb = t; bb < BHALF; bb += 256)
        se += __expf(fabsf(pro_i[bb] - pro_j[bb]) - mx);
    sred[t] = se;
    __syncthreads();
    for (int off = 128; off > 0; off >>= 1) {
        if (t < off) sred[t] += sred[t + off];
        __syncthreads();
    }
    const float invZ = 1.0f / sred[0];
    __syncthreads();

    float lp = 0.0f;
    for (int bb = t; bb < BHALF; bb += 256) {
        float pdv = fabsf(pro_i[bb] - pro_j[bb]);
        lp += __logf(__expf(pdv - mx) * invZ + TEMP_EPS);
        lp += __logf(1.0f + fabsf(emb_i[bb] - emb_j[bb]));
    }
    sred[t] = lp;
    __syncthreads();
    for (int off = 128; off > 0; off >>= 1) {
        if (t < off) sred[t] += sred[t + off];
        __syncthreads();
    }
    if (t == 0) g_tail = sred[0];
}

// ---------------------------------------------------------------------------
// Kernel C: final combine. 1 block, 64 threads.
// ---------------------------------------------------------------------------
__global__ __launch_bounds__(64) void combine_kernel(float* __restrict__ out)
{
    __shared__ float sred[64];
    const int t = threadIdx.x;
    sred[t] = g_blocksum[t];
    __syncthreads();
    for (int off = 32; off > 0; off >>= 1) {
        if (t < off) sred[t] += sred[t + off];
        __syncthreads();
    }
    if (t == 0) out[0] = (sred[0] + 2.0f * g_tail) / (float)N;
}

// ---------------------------------------------------------------------------
extern "C" void kernel_launch(void* const* d_in, const int* in_sizes, int n_in,
                              void* d_out, int out_size)
{
    const float* emb_i = (const float*)d_in[0];
    const float* emb_j = (const float*)d_in[1];
    const float* pro_i = (const float*)d_in[2];
    const float* pro_j = (const float*)d_in[3];
    float* out = (float*)d_out;

    tile_kernel<<<NTRI, 256>>>(emb_i, emb_j);
    reduce_kernel<<<65, 256>>>(emb_i, emb_j, pro_i, pro_j);
    combine_kernel<<<1, 64>>>(out);
}

// round 8
// speedup vs baseline: 1.5842x; 1.0900x over previous
#include <cuda_runtime.h>
#include <math.h>
#include <stdint.h>

// Problem constants
#define BHALF 8192            // B
#define N     16384           // 2B
#define TILE  128
#define NT    (N / TILE)      // 128 tiles
#define NTRI  (NT * (NT + 1) / 2)        // 8256 triangular blocks
#define EXPDIAG 7.389056098930650f       // exp(2) = exp(sim_ii / T)
#define NEG_INV_C (-0.34657359027997264f) // -1/(2*log2(e)) = -ln2/2
#define TEMP_EPS 0.01f

// Scratch (deterministic: every slot has exactly one writer)
__device__ float g_part[NT * N];          // 8 MB partial row sums (L2-resident)
__device__ float g_blocksum[64];
__device__ float g_tail;

// ---------------- packed f32x2 helpers (sm_100 family) ----------------
__device__ __forceinline__ unsigned long long pk2(float lo, float hi) {
    unsigned long long r;
    asm("mov.b64 %0, {%1, %2};" : "=l"(r) : "f"(lo), "f"(hi));
    return r;
}
__device__ __forceinline__ float lo2(unsigned long long v) {
    float f; asm("{ .reg .f32 t; mov.b64 {%0, t}, %1; }" : "=f"(f) : "l"(v)); return f;
}
__device__ __forceinline__ float hi2(unsigned long long v) {
    float f; asm("{ .reg .f32 t; mov.b64 {t, %0}, %1; }" : "=f"(f) : "l"(v)); return f;
}
__device__ __forceinline__ unsigned long long add2(unsigned long long a, unsigned long long b) {
    unsigned long long r;
    asm("add.rn.f32x2 %0, %1, %2;" : "=l"(r) : "l"(a), "l"(b));
    return r;
}
__device__ __forceinline__ unsigned long long mul2(unsigned long long a, unsigned long long b) {
    unsigned long long r;
    asm("mul.rn.f32x2 %0, %1, %2;" : "=l"(r) : "l"(a), "l"(b));
    return r;
}
__device__ __forceinline__ unsigned long long fma2(unsigned long long a, unsigned long long b,
                                                   unsigned long long c) {
    unsigned long long r;
    asm("fma.rn.f32x2 %0, %1, %2, %3;" : "=l"(r) : "l"(a), "l"(b), "l"(c));
    return r;
}
__device__ __forceinline__ float ex2a(float x) {
    float r;
    asm("ex2.approx.ftz.f32 %0, %1;" : "=f"(r) : "f"(x));
    return r;
}

// ---------------------------------------------------------------------------
// Kernel A: symmetric tile kernel. Same structure as the proven 56.8us
// version, with ONE Newton iteration on the bit-hack reciprocal (error
// budget: one-sided -err^2 <= 0.26% on r -> ~1e-4 on the final loss, vs
// 1e-3 threshold). Per 2 pairs: 6 fma-pipe ops + ~4 alu + 2 MUFU.EX2 ->
// MUFU is now the single binding pipe (16 cyc / 2 pairs).
// ---------------------------------------------------------------------------
__global__ __launch_bounds__(256, 3) void tile_kernel(
    const float* __restrict__ emb_i, const float* __restrict__ emb_j)
{
    // decode triangular (a, b) from linear block id
    const int k = blockIdx.x;
    float disc = (float)((2 * NT + 1) * (2 * NT + 1) - 8 * k);
    int a = (int)(((float)(2 * NT + 1) - sqrtf(disc)) * 0.5f);
    a = max(0, min(a, NT - 1));
    while (a > 0 && k < a * NT - (a * (a - 1)) / 2) a--;
    while (k >= (a + 1) * NT - ((a + 1) * a) / 2) a++;
    const int b = a + (k - (a * NT - (a * (a - 1)) / 2));

    __shared__ float ra[TILE];
    __shared__ float rbn[TILE];           // NEGATED b-tile values
    __shared__ float red[16][TILE + 1];

    const int t = threadIdx.x;

    if (t < TILE) {
        int g = a * TILE + t;
        ra[t] = (g < BHALF) ? emb_i[g] : emb_j[g - BHALF];
    } else {
        int t2 = t - TILE;
        int g = b * TILE + t2;
        float v = (g < BHALF) ? emb_i[g] : emb_j[g - BHALF];
        rbn[t2] = -v;
    }
    __syncthreads();

    const int tx = t & 15;
    const int ty = t >> 4;

    float riS[8];
    unsigned long long rjn[4];
#pragma unroll
    for (int y = 0; y < 8; y++) riS[y] = ra[ty * 8 + y];
#pragma unroll
    for (int x2 = 0; x2 < 4; x2++)
        rjn[x2] = pk2(rbn[tx * 8 + 2 * x2], rbn[tx * 8 + 2 * x2 + 1]);

    const unsigned long long cN   = pk2(NEG_INV_C, NEG_INV_C);
    const unsigned long long two2 = pk2(2.0f, 2.0f);

    unsigned long long rowP[8], colP[4];
#pragma unroll
    for (int y = 0; y < 8; y++) rowP[y] = 0ULL;
#pragma unroll
    for (int x2 = 0; x2 < 4; x2++) colP[x2] = 0ULL;

#pragma unroll
    for (int y = 0; y < 8; y++) {
        const unsigned long long rip = pk2(riS[y], riS[y]);  // built per-y: saves regs
#pragma unroll
        for (int x2 = 0; x2 < 4; x2++) {
            unsigned long long df = add2(rip, rjn[x2]);              // ri - rj
            df &= 0x7FFFFFFF7FFFFFFFULL;                              // |.| per half
            unsigned long long sn = fma2(df, cN, cN);                 // -(1+d)/C
            uint32_t bl = (uint32_t)sn;
            uint32_t bh = (uint32_t)(sn >> 32);
            unsigned long long r = pk2(__uint_as_float(0xFEF311C3u - bl),
                                       __uint_as_float(0xFEF311C3u - bh));
            unsigned long long tt = fma2(sn, r, two2);                // 2 - |s|r
            r = mul2(r, tt);                                          // 1 Newton step
            unsigned long long e2 = pk2(ex2a(lo2(r)), ex2a(hi2(r)));
            rowP[y]  = add2(rowP[y],  e2);
            colP[x2] = add2(colP[x2], e2);
        }
    }

    // --- deterministic row-partial reduction (across the 16 thread-cols) ---
#pragma unroll
    for (int y = 0; y < 8; y++)
        red[tx][ty * 8 + y] = lo2(rowP[y]) + hi2(rowP[y]);
    __syncthreads();
    if (t < TILE) {
        float s = 0.0f;
#pragma unroll
        for (int kk = 0; kk < 16; kk++) s += red[kk][t];
        g_part[b * N + a * TILE + t] = s;
    }
    __syncthreads();

    // --- deterministic col-partial reduction (across the 16 thread-rows) ---
#pragma unroll
    for (int x2 = 0; x2 < 4; x2++) {
        red[ty][tx * 8 + 2 * x2]     = lo2(colP[x2]);
        red[ty][tx * 8 + 2 * x2 + 1] = hi2(colP[x2]);
    }
    __syncthreads();
    if (a != b && t < TILE) {
        float s = 0.0f;
#pragma unroll
        for (int kk = 0; kk < 16; kk++) s += red[kk][t];
        g_part[a * N + b * TILE + t] = s;
    }
}

// ---------------------------------------------------------------------------
// Kernel B: 65 blocks x 256 threads (R4-proven tail).
//   blocks 0..63 : per-row denominator -> __logf -> block sum  (256 rows each)
//   block 64     : prosody softmax + positives tail (fast intrinsics)
// ---------------------------------------------------------------------------
__global__ __launch_bounds__(256) void reduce_kernel(
    const float* __restrict__ emb_i, const float* __restrict__ emb_j,
    const float* __restrict__ pro_i, const float* __restrict__ pro_j)
{
    __shared__ float sred[256];
    const int t = threadIdx.x;
    const int role = blockIdx.x;

    if (role < 64) {
        // ---- row-log reduction: rows [role*256, role*256+256) ----
        const int i = role * 256 + t;
        float s = 0.0f;
#pragma unroll 16
        for (int kk = 0; kk < NT; kk++) s += g_part[kk * N + i];
        sred[t] = __logf(s - EXPDIAG);        // remove diagonal term exp(2)
        __syncthreads();
        for (int off = 128; off > 0; off >>= 1) {
            if (t < off) sred[t] += sred[t + off];
            __syncthreads();
        }
        if (t == 0) g_blocksum[role] = sred[0];
        return;
    }

    // ---- prosody softmax + positives tail (block 64) ----
    float mx = -1.0f;
    for (int bb = t; bb < BHALF; bb += 256)
        mx = fmaxf(mx, fabsf(pro_i[bb] - pro_j[bb]));
    sred[t] = mx;
    __syncthreads();
    for (int off = 128; off > 0; off >>= 1) {
        if (t < off) sred[t] = fmaxf(sred[t], sred[t + off]);
        __syncthreads();
    }
    mx = sred[0];
    __syncthreads();

    float se = 0.0f;
    for (int bb = t; bb < BHALF; bb += 256)
        se += __expf(fabsf(pro_i[bb] - pro_j[bb]) - mx);
    sred[t] = se;
    __syncthreads();
    for (int off = 128; off > 0; off >>= 1) {
        if (t < off) sred[t] += sred[t + off];
        __syncthreads();
    }
    const float invZ = 1.0f / sred[0];
    __syncthreads();

    float lp = 0.0f;
    for (int bb = t; bb < BHALF; bb += 256) {
        float pdv = fabsf(pro_i[bb] - pro_j[bb]);
        lp += __logf(__expf(pdv - mx) * invZ + TEMP_EPS);
        lp += __logf(1.0f + fabsf(emb_i[bb] - emb_j[bb]));
    }
    sred[t] = lp;
    __syncthreads();
    for (int off = 128; off > 0; off >>= 1) {
        if (t < off) sred[t] += sred[t + off];
        __syncthreads();
    }
    if (t == 0) g_tail = sred[0];
}

// ---------------------------------------------------------------------------
// Kernel C: final combine. 1 block, 64 threads.
// ---------------------------------------------------------------------------
__global__ __launch_bounds__(64) void combine_kernel(float* __restrict__ out)
{
    __shared__ float sred[64];
    const int t = threadIdx.x;
    sred[t] = g_blocksum[t];
    __syncthreads();
    for (int off = 32; off > 0; off >>= 1) {
        if (t < off) sred[t] += sred[t + off];
        __syncthreads();
    }
    if (t == 0) out[0] = (sred[0] + 2.0f * g_tail) / (float)N;
}

// ---------------------------------------------------------------------------
extern "C" void kernel_launch(void* const* d_in, const int* in_sizes, int n_in,
                              void* d_out, int out_size)
{
    const float* emb_i = (const float*)d_in[0];
    const float* emb_j = (const float*)d_in[1];
    const float* pro_i = (const float*)d_in[2];
    const float* pro_j = (const float*)d_in[3];
    float* out = (float*)d_out;

    tile_kernel<<<NTRI, 256>>>(emb_i, emb_j);
    reduce_kernel<<<65, 256>>>(emb_i, emb_j, pro_i, pro_j);
    combine_kernel<<<1, 64>>>(out);
}

// round 9
// speedup vs baseline: 1.6703x; 1.0544x over previous
#include <cuda_runtime.h>
#include <math.h>
#include <stdint.h>

// Problem constants
#define BHALF 8192            // B
#define N     16384           // 2B
#define TILE  128
#define NT    (N / TILE)      // 128 tiles
#define NTRI  (NT * (NT + 1) / 2)        // 8256 triangular blocks
#define EXPDIAG 7.389056098930650f       // exp(2) = exp(sim_ii / T)
#define NEG_INV_C (-0.34657359027997264f) // -1/(2*log2(e)) = -ln2/2
#define TEMP_EPS 0.01f
// Newton constant with bias recentering: 2 + mean(seed_err^2) cancels the
// one-sided -eps^2 error of the single Newton step (calibrated from R8's
// measured 2.5e-4 loss bias).
#define TWO_CORR 2.000122f

// Scratch (deterministic: every slot has exactly one writer)
__device__ float g_part[NT * N];          // 8 MB partial row sums (L2-resident)
__device__ float g_blocksum[64];
__device__ float g_tail;

// ---------------- packed f32x2 helpers (sm_100 family) ----------------
__device__ __forceinline__ unsigned long long pk2(float lo, float hi) {
    unsigned long long r;
    asm("mov.b64 %0, {%1, %2};" : "=l"(r) : "f"(lo), "f"(hi));
    return r;
}
__device__ __forceinline__ float lo2(unsigned long long v) {
    float f; asm("{ .reg .f32 t; mov.b64 {%0, t}, %1; }" : "=f"(f) : "l"(v)); return f;
}
__device__ __forceinline__ float hi2(unsigned long long v) {
    float f; asm("{ .reg .f32 t; mov.b64 {t, %0}, %1; }" : "=f"(f) : "l"(v)); return f;
}
__device__ __forceinline__ unsigned long long add2(unsigned long long a, unsigned long long b) {
    unsigned long long r;
    asm("add.rn.f32x2 %0, %1, %2;" : "=l"(r) : "l"(a), "l"(b));
    return r;
}
__device__ __forceinline__ unsigned long long mul2(unsigned long long a, unsigned long long b) {
    unsigned long long r;
    asm("mul.rn.f32x2 %0, %1, %2;" : "=l"(r) : "l"(a), "l"(b));
    return r;
}
__device__ __forceinline__ unsigned long long fma2(unsigned long long a, unsigned long long b,
                                                   unsigned long long c) {
    unsigned long long r;
    asm("fma.rn.f32x2 %0, %1, %2, %3;" : "=l"(r) : "l"(a), "l"(b), "l"(c));
    return r;
}
__device__ __forceinline__ float ex2a(float x) {
    float r;
    asm("ex2.approx.ftz.f32 %0, %1;" : "=f"(r) : "f"(x));
    return r;
}

// ---------------------------------------------------------------------------
// Kernel A: symmetric tile kernel. Single-Newton bit-hack reciprocal with
// bias-recentered constant. __launch_bounds__(256,4) caps regs at 64 -> 4
// resident blocks = 8 warps/SMSP, enough eligible warps to keep MUFU.EX2
// (the binding pipe: 2 ops / 2 pairs = 16 cyc) saturated.
// ri values are re-loaded from shared per y-iteration to stay under the cap.
// ---------------------------------------------------------------------------
__global__ __launch_bounds__(256, 4) void tile_kernel(
    const float* __restrict__ emb_i, const float* __restrict__ emb_j)
{
    // decode triangular (a, b) from linear block id
    const int k = blockIdx.x;
    float disc = (float)((2 * NT + 1) * (2 * NT + 1) - 8 * k);
    int a = (int)(((float)(2 * NT + 1) - sqrtf(disc)) * 0.5f);
    a = max(0, min(a, NT - 1));
    while (a > 0 && k < a * NT - (a * (a - 1)) / 2) a--;
    while (k >= (a + 1) * NT - ((a + 1) * a) / 2) a++;
    const int b = a + (k - (a * NT - (a * (a - 1)) / 2));

    __shared__ float ra[TILE];
    __shared__ float rbn[TILE];           // NEGATED b-tile values
    __shared__ float red[16][TILE + 1];

    const int t = threadIdx.x;

    if (t < TILE) {
        int g = a * TILE + t;
        ra[t] = (g < BHALF) ? emb_i[g] : emb_j[g - BHALF];
    } else {
        int t2 = t - TILE;
        int g = b * TILE + t2;
        float v = (g < BHALF) ? emb_i[g] : emb_j[g - BHALF];
        rbn[t2] = -v;
    }
    __syncthreads();

    const int tx = t & 15;
    const int ty = t >> 4;

    unsigned long long rjn[4];
#pragma unroll
    for (int x2 = 0; x2 < 4; x2++)
        rjn[x2] = pk2(rbn[tx * 8 + 2 * x2], rbn[tx * 8 + 2 * x2 + 1]);

    const unsigned long long cN   = pk2(NEG_INV_C, NEG_INV_C);
    const unsigned long long two2 = pk2(TWO_CORR, TWO_CORR);

    unsigned long long rowP[8], colP[4];
#pragma unroll
    for (int y = 0; y < 8; y++) rowP[y] = 0ULL;
#pragma unroll
    for (int x2 = 0; x2 < 4; x2++) colP[x2] = 0ULL;

#pragma unroll
    for (int y = 0; y < 8; y++) {
        const float riv = ra[ty * 8 + y];          // per-y LDS: saves 8 regs
        const unsigned long long rip = pk2(riv, riv);
#pragma unroll
        for (int x2 = 0; x2 < 4; x2++) {
            unsigned long long df = add2(rip, rjn[x2]);              // ri - rj
            df &= 0x7FFFFFFF7FFFFFFFULL;                              // |.| per half
            unsigned long long sn = fma2(df, cN, cN);                 // -(1+d)/C
            uint32_t bl = (uint32_t)sn;
            uint32_t bh = (uint32_t)(sn >> 32);
            unsigned long long r = pk2(__uint_as_float(0xFEF311C3u - bl),
                                       __uint_as_float(0xFEF311C3u - bh));
            unsigned long long tt = fma2(sn, r, two2);                // (2+delta) - |s|r
            r = mul2(r, tt);                                          // 1 Newton, recentered
            unsigned long long e2 = pk2(ex2a(lo2(r)), ex2a(hi2(r)));
            rowP[y]  = add2(rowP[y],  e2);
            colP[x2] = add2(colP[x2], e2);
        }
    }

    // --- deterministic row-partial reduction (across the 16 thread-cols) ---
#pragma unroll
    for (int y = 0; y < 8; y++)
        red[tx][ty * 8 + y] = lo2(rowP[y]) + hi2(rowP[y]);
    __syncthreads();
    if (t < TILE) {
        float s = 0.0f;
#pragma unroll
        for (int kk = 0; kk < 16; kk++) s += red[kk][t];
        g_part[b * N + a * TILE + t] = s;
    }
    __syncthreads();

    // --- deterministic col-partial reduction (across the 16 thread-rows) ---
#pragma unroll
    for (int x2 = 0; x2 < 4; x2++) {
        red[ty][tx * 8 + 2 * x2]     = lo2(colP[x2]);
        red[ty][tx * 8 + 2 * x2 + 1] = hi2(colP[x2]);
    }
    __syncthreads();
    if (a != b && t < TILE) {
        float s = 0.0f;
#pragma unroll
        for (int kk = 0; kk < 16; kk++) s += red[kk][t];
        g_part[a * N + b * TILE + t] = s;
    }
}

// ---------------------------------------------------------------------------
// Kernel B: 65 blocks x 256 threads (R4-proven tail).
//   blocks 0..63 : per-row denominator -> __logf -> block sum  (256 rows each)
//   block 64     : prosody softmax + positives tail (fast intrinsics)
// ---------------------------------------------------------------------------
__global__ __launch_bounds__(256) void reduce_kernel(
    const float* __restrict__ emb_i, const float* __restrict__ emb_j,
    const float* __restrict__ pro_i, const float* __restrict__ pro_j)
{
    __shared__ float sred[256];
    const int t = threadIdx.x;
    const int role = blockIdx.x;

    if (role < 64) {
        // ---- row-log reduction: rows [role*256, role*256+256) ----
        const int i = role * 256 + t;
        float s = 0.0f;
#pragma unroll 16
        for (int kk = 0; kk < NT; kk++) s += g_part[kk * N + i];
        sred[t] = __logf(s - EXPDIAG);        // remove diagonal term exp(2)
        __syncthreads();
        for (int off = 128; off > 0; off >>= 1) {
            if (t < off) sred[t] += sred[t + off];
            __syncthreads();
        }
        if (t == 0) g_blocksum[role] = sred[0];
        return;
    }

    // ---- prosody softmax + positives tail (block 64) ----
    float mx = -1.0f;
    for (int bb = t; bb < BHALF; bb += 256)
        mx = fmaxf(mx, fabsf(pro_i[bb] - pro_j[bb]));
    sred[t] = mx;
    __syncthreads();
    for (int off = 128; off > 0; off >>= 1) {
        if (t < off) sred[t] = fmaxf(sred[t], sred[t + off]);
        __syncthreads();
    }
    mx = sred[0];
    __syncthreads();

    float se = 0.0f;
    for (int bb = t; bb < BHALF; bb += 256)
        se += __expf(fabsf(pro_i[bb] - pro_j[bb]) - mx);
    sred[t] = se;
    __syncthreads();
    for (int off = 128; off > 0; off >>= 1) {
        if (t < off) sred[t] += sred[t + off];
        __syncthreads();
    }
    const float invZ = 1.0f / sred[0];
    __syncthreads();

    float lp = 0.0f;
    for (int bb = t; bb < BHALF; bb += 256) {
        float pdv = fabsf(pro_i[bb] - pro_j[bb]);
        lp += __logf(__expf(pdv - mx) * invZ + TEMP_EPS);
        lp += __logf(1.0f + fabsf(emb_i[bb] - emb_j[bb]));
    }
    sred[t] = lp;
    __syncthreads();
    for (int off = 128; off > 0; off >>= 1) {
        if (t < off) sred[t] += sred[t + off];
        __syncthreads();
    }
    if (t == 0) g_tail = sred[0];
}

// ---------------------------------------------------------------------------
// Kernel C: final combine. 1 block, 64 threads.
// ---------------------------------------------------------------------------
__global__ __launch_bounds__(64) void combine_kernel(float* __restrict__ out)
{
    __shared__ float sred[64];
    const int t = threadIdx.x;
    sred[t] = g_blocksum[t];
    __syncthreads();
    for (int off = 32; off > 0; off >>= 1) {
        if (t < off) sred[t] += sred[t + off];
        __syncthreads();
    }
    if (t == 0) out[0] = (sred[0] + 2.0f * g_tail) / (float)N;
}

// ---------------------------------------------------------------------------
extern "C" void kernel_launch(void* const* d_in, const int* in_sizes, int n_in,
                              void* d_out, int out_size)
{
    const float* emb_i = (const float*)d_in[0];
    const float* emb_j = (const float*)d_in[1];
    const float* pro_i = (const float*)d_in[2];
    const float* pro_j = (const float*)d_in[3];
    float* out = (float*)d_out;

    tile_kernel<<<NTRI, 256>>>(emb_i, emb_j);
    reduce_kernel<<<65, 256>>>(emb_i, emb_j, pro_i, pro_j);
    combine_kernel<<<1, 64>>>(out);
}

// round 10
// speedup vs baseline: 1.7345x; 1.0384x over previous
#include <cuda_runtime.h>
#include <math.h>
#include <stdint.h>

// Problem constants
#define BHALF 8192            // B
#define N     16384           // 2B
#define TILE  128
#define NT    (N / TILE)      // 128 tiles
#define NTRI  (NT * (NT + 1) / 2)        // 8256 triangular blocks
#define EXPDIAG 7.389056098930650f       // exp(2) = exp(sim_ii / T)
#define NEG_INV_C (-0.34657359027997264f) // -1/(2*log2(e)) = -ln2/2
#define TEMP_EPS 0.01f
#define TWO_CORR 2.000122f   // Newton constant, bias-recentered (R8 calib)

// Scratch (deterministic: every slot has exactly one writer)
__device__ float g_part[NT * N];          // 8 MB partial row sums (L2-resident)
__device__ float g_blocksum[64];
__device__ float g_tail;

// ---------------- packed f32x2 helpers (sm_100 family) ----------------
__device__ __forceinline__ unsigned long long pk2(float lo, float hi) {
    unsigned long long r;
    asm("mov.b64 %0, {%1, %2};" : "=l"(r) : "f"(lo), "f"(hi));
    return r;
}
__device__ __forceinline__ float lo2(unsigned long long v) {
    float f; asm("{ .reg .f32 t; mov.b64 {%0, t}, %1; }" : "=f"(f) : "l"(v)); return f;
}
__device__ __forceinline__ float hi2(unsigned long long v) {
    float f; asm("{ .reg .f32 t; mov.b64 {t, %0}, %1; }" : "=f"(f) : "l"(v)); return f;
}
__device__ __forceinline__ unsigned long long add2(unsigned long long a, unsigned long long b) {
    unsigned long long r;
    asm("add.rn.f32x2 %0, %1, %2;" : "=l"(r) : "l"(a), "l"(b));
    return r;
}
__device__ __forceinline__ unsigned long long mul2(unsigned long long a, unsigned long long b) {
    unsigned long long r;
    asm("mul.rn.f32x2 %0, %1, %2;" : "=l"(r) : "l"(a), "l"(b));
    return r;
}
__device__ __forceinline__ unsigned long long fma2(unsigned long long a, unsigned long long b,
                                                   unsigned long long c) {
    unsigned long long r;
    asm("fma.rn.f32x2 %0, %1, %2, %3;" : "=l"(r) : "l"(a), "l"(b), "l"(c));
    return r;
}
__device__ __forceinline__ float ex2a(float x) {
    float r;
    asm("ex2.approx.ftz.f32 %0, %1;" : "=f"(r) : "f"(x));
    return r;
}

// ---------------------------------------------------------------------------
// Kernel A: symmetric tile kernel. Single-Newton bit-hack reciprocal
// (bias-recentered). Register diet for 5 blocks/SM (cap 51):
//  - ri re-read from shared per y-iteration
//  - rj pairs pre-packed & NEGATED in a padded smem array (stride 5 ull =
//    40 B -> banks (tx*10+2*x2)%32 all distinct -> conflict-free LDS.64)
//  - row and col epilogue reductions fused behind ONE barrier (2 buffers)
// Per 2 pairs: 6 fma-pipe + ~4 alu + 1 LDS.64 + 2 MUFU.EX2.
// ---------------------------------------------------------------------------
__global__ __launch_bounds__(256, 5) void tile_kernel(
    const float* __restrict__ emb_i, const float* __restrict__ emb_j)
{
    // decode triangular (a, b) from linear block id
    const int k = blockIdx.x;
    float disc = (float)((2 * NT + 1) * (2 * NT + 1) - 8 * k);
    int a = (int)(((float)(2 * NT + 1) - sqrtf(disc)) * 0.5f);
    a = max(0, min(a, NT - 1));
    while (a > 0 && k < a * NT - (a * (a - 1)) / 2) a--;
    while (k >= (a + 1) * NT - ((a + 1) * a) / 2) a++;
    const int b = a + (k - (a * NT - (a * (a - 1)) / 2));

    __shared__ float ra[TILE];
    __shared__ unsigned long long rbn_pad[16][5];   // packed (-rj0,-rj1), padded
    __shared__ float redR[16][TILE + 1];            // row-reduction scratch
    __shared__ float redC[16][TILE + 1];            // col-reduction scratch

    const int t = threadIdx.x;

    // ---- load rep values ----
    if (t < TILE) {
        int g = a * TILE + t;
        ra[t] = (g < BHALF) ? emb_i[g] : emb_j[g - BHALF];
    } else if (t < TILE + 64) {
        // pair j = t-128 covers b-tile cols 2j, 2j+1 (tile never crosses the
        // emb_i/emb_j boundary: BHALF is a multiple of TILE)
        int j = t - TILE;
        int gi = b * TILE + 2 * j;
        float2 v = (gi < BHALF)
                 ? ((const float2*)emb_i)[gi >> 1]
                 : ((const float2*)emb_j)[(gi - BHALF) >> 1];
        rbn_pad[j >> 2][j & 3] = pk2(-v.x, -v.y);
    }
    __syncthreads();

    const int tx = t & 15;
    const int ty = t >> 4;

    const unsigned long long cN   = pk2(NEG_INV_C, NEG_INV_C);
    const unsigned long long two2 = pk2(TWO_CORR, TWO_CORR);

    unsigned long long rowP[8], colP[4];
#pragma unroll
    for (int y = 0; y < 8; y++) rowP[y] = 0ULL;
#pragma unroll
    for (int x2 = 0; x2 < 4; x2++) colP[x2] = 0ULL;

#pragma unroll
    for (int y = 0; y < 8; y++) {
        const float riv = ra[ty * 8 + y];
        const unsigned long long rip = pk2(riv, riv);
#pragma unroll
        for (int x2 = 0; x2 < 4; x2++) {
            unsigned long long rjnv = rbn_pad[tx][x2];               // LDS.64, no conflicts
            unsigned long long df = add2(rip, rjnv);                  // ri - rj
            df &= 0x7FFFFFFF7FFFFFFFULL;                              // |.| per half
            unsigned long long sn = fma2(df, cN, cN);                 // -(1+d)/C
            uint32_t bl = (uint32_t)sn;
            uint32_t bh = (uint32_t)(sn >> 32);
            unsigned long long r = pk2(__uint_as_float(0xFEF311C3u - bl),
                                       __uint_as_float(0xFEF311C3u - bh));
            unsigned long long tt = fma2(sn, r, two2);                // (2+d) - |s|r
            r = mul2(r, tt);                                          // 1 Newton, recentered
            unsigned long long e2 = pk2(ex2a(lo2(r)), ex2a(hi2(r)));
            rowP[y]  = add2(rowP[y],  e2);
            colP[x2] = add2(colP[x2], e2);
        }
    }

    // ---- fused epilogue: both scratch writes, ONE barrier, both outputs ----
#pragma unroll
    for (int y = 0; y < 8; y++)
        redR[tx][ty * 8 + y] = lo2(rowP[y]) + hi2(rowP[y]);
#pragma unroll
    for (int x2 = 0; x2 < 4; x2++) {
        redC[ty][tx * 8 + 2 * x2]     = lo2(colP[x2]);
        redC[ty][tx * 8 + 2 * x2 + 1] = hi2(colP[x2]);
    }
    __syncthreads();
    if (t < TILE) {
        float sr = 0.0f;
#pragma unroll
        for (int kk = 0; kk < 16; kk++) sr += redR[kk][t];
        g_part[b * N + a * TILE + t] = sr;
        if (a != b) {
            float sc = 0.0f;
#pragma unroll
            for (int kk = 0; kk < 16; kk++) sc += redC[kk][t];
            g_part[a * N + b * TILE + t] = sc;
        }
    }
}

// ---------------------------------------------------------------------------
// Kernel B: 65 blocks x 256 threads (proven tail).
//   blocks 0..63 : per-row denominator -> __logf -> block sum  (256 rows each)
//   block 64     : prosody softmax + positives tail (fast intrinsics)
// ---------------------------------------------------------------------------
__global__ __launch_bounds__(256) void reduce_kernel(
    const float* __restrict__ emb_i, const float* __restrict__ emb_j,
    const float* __restrict__ pro_i, const float* __restrict__ pro_j)
{
    __shared__ float sred[256];
    const int t = threadIdx.x;
    const int role = blockIdx.x;

    if (role < 64) {
        // ---- row-log reduction: rows [role*256, role*256+256) ----
        const int i = role * 256 + t;
        float s = 0.0f;
#pragma unroll 16
        for (int kk = 0; kk < NT; kk++) s += g_part[kk * N + i];
        sred[t] = __logf(s - EXPDIAG);        // remove diagonal term exp(2)
        __syncthreads();
        for (int off = 128; off > 0; off >>= 1) {
            if (t < off) sred[t] += sred[t + off];
            __syncthreads();
        }
        if (t == 0) g_blocksum[role] = sred[0];
        return;
    }

    // ---- prosody softmax + positives tail (block 64) ----
    float mx = -1.0f;
    for (int bb = t; bb < BHALF; bb += 256)
        mx = fmaxf(mx, fabsf(pro_i[bb] - pro_j[bb]));
    sred[t] = mx;
    __syncthreads();
    for (int off = 128; off > 0; off >>= 1) {
        if (t < off) sred[t] = fmaxf(sred[t], sred[t + off]);
        __syncthreads();
    }
    mx = sred[0];
    __syncthreads();

    float se = 0.0f;
    for (int bb = t; bb < BHALF; bb += 256)
        se += __expf(fabsf(pro_i[bb] - pro_j[bb]) - mx);
    sred[t] = se;
    __syncthreads();
    for (int off = 128; off > 0; off >>= 1) {
        if (t < off) sred[t] += sred[t + off];
        __syncthreads();
    }
    const float invZ = 1.0f / sred[0];
    __syncthreads();

    float lp = 0.0f;
    for (int bb = t; bb < BHALF; bb += 256) {
        float pdv = fabsf(pro_i[bb] - pro_j[bb]);
        lp += __logf(__expf(pdv - mx) * invZ + TEMP_EPS);
        lp += __logf(1.0f + fabsf(emb_i[bb] - emb_j[bb]));
    }
    sred[t] = lp;
    __syncthreads();
    for (int off = 128; off > 0; off >>= 1) {
        if (t < off) sred[t] += sred[t + off];
        __syncthreads();
    }
    if (t == 0) g_tail = sred[0];
}

// ---------------------------------------------------------------------------
// Kernel C: final combine. 1 block, 64 threads.
// ---------------------------------------------------------------------------
__global__ __launch_bounds__(64) void combine_kernel(float* __restrict__ out)
{
    __shared__ float sred[64];
    const int t = threadIdx.x;
    sred[t] = g_blocksum[t];
    __syncthreads();
    for (int off = 32; off > 0; off >>= 1) {
        if (t < off) sred[t] += sred[t + off];
        __syncthreads();
    }
    if (t == 0) out[0] = (sred[0] + 2.0f * g_tail) / (float)N;
}

// ---------------------------------------------------------------------------
extern "C" void kernel_launch(void* const* d_in, const int* in_sizes, int n_in,
                              void* d_out, int out_size)
{
    const float* emb_i = (const float*)d_in[0];
    const float* emb_j = (const float*)d_in[1];
    const float* pro_i = (const float*)d_in[2];
    const float* pro_j = (const float*)d_in[3];
    float* out = (float*)d_out;

    tile_kernel<<<NTRI, 256>>>(emb_i, emb_j);
    reduce_kernel<<<65, 256>>>(emb_i, emb_j, pro_i, pro_j);
    combine_kernel<<<1, 64>>>(out);
}